// round 1
// baseline (speedup 1.0000x reference)
#include <cuda_runtime.h>
#include <math.h>

#define N_ROI 256
#define CCH   256
#define DIN   12544   // 256*49
#define DH    4096
#define NLOC  84
#define NCLS  21

// Scratch (no allocations allowed in kernel_launch)
__device__ float g_pooled[N_ROI * DIN];
__device__ float g_fc6[N_ROI * DH];
__device__ float g_fc7[N_ROI * DH];

// ---------------------------------------------------------------------------
// RoI max-pool over FPN levels. One block per roi, one thread per channel.
// ---------------------------------------------------------------------------
__global__ void roi_pool_kernel(const float* __restrict__ f3,
                                const float* __restrict__ f4,
                                const float* __restrict__ f5,
                                const float* __restrict__ rois,
                                float* __restrict__ pooled)
{
    const int n = blockIdx.x;
    const int c = threadIdx.x;

    const float y1 = rois[n * 4 + 0];
    const float x1 = rois[n * 4 + 1];
    const float y2 = rois[n * 4 + 2];
    const float x2 = rois[n * 4 + 3];

    const float Hr = y2 - y1;
    const float Wr = x2 - x1;
    // level = clip(round(log(sqrt(HW)/224)+5), 3, 5) - 3 ; rintf = round-half-even, matches jnp.round
    float lv = rintf(logf(sqrtf(Hr * Wr) / 224.0f) + 5.0f);
    lv = fminf(fmaxf(lv, 3.0f), 5.0f);
    const int l = (int)lv - 3;

    const float scale = (l == 0) ? 0.125f : (l == 1 ? 0.0625f : 0.03125f);
    const int   hw    = (l == 0) ? 100    : (l == 1 ? 50      : 25);
    const float* fmap = (l == 0) ? f3     : (l == 1 ? f4      : f5);
    fmap += (size_t)c * hw * hw;

    // torchvision roi_pool rounding: floor(x + 0.5)
    const float ys = floorf(y1 * scale + 0.5f);
    const float xs = floorf(x1 * scale + 0.5f);
    const float ye = floorf(y2 * scale + 0.5f);
    const float xe = floorf(x2 * scale + 0.5f);
    const float bh = fmaxf(ye - ys + 1.0f, 1.0f) * (1.0f / 7.0f);
    const float bw = fmaxf(xe - xs + 1.0f, 1.0f) * (1.0f / 7.0f);

    float* orow = pooled + (size_t)n * DIN + (size_t)c * 49;

    #pragma unroll
    for (int ph = 0; ph < 7; ph++) {
        int h0 = (int)fminf(fmaxf(floorf((float)ph * bh) + ys, 0.0f), (float)hw);
        int h1 = (int)fminf(fmaxf(ceilf((float)(ph + 1) * bh) + ys, 0.0f), (float)hw);
        #pragma unroll
        for (int pw = 0; pw < 7; pw++) {
            int w0 = (int)fminf(fmaxf(floorf((float)pw * bw) + xs, 0.0f), (float)hw);
            int w1 = (int)fminf(fmaxf(ceilf((float)(pw + 1) * bw) + xs, 0.0f), (float)hw);
            float m;
            if (h1 <= h0 || w1 <= w0) {
                m = 0.0f;
            } else {
                m = -INFINITY;
                for (int r = h0; r < h1; r++) {
                    const float* rowp = fmap + r * hw;
                    for (int q = w0; q < w1; q++)
                        m = fmaxf(m, rowp[q]);
                }
            }
            orow[ph * 7 + pw] = m;
        }
    }
}

// ---------------------------------------------------------------------------
// Tiled fp32 GEMM: C[M,N] = relu?(A[M,K] @ B[K,N] + bias[N])
// BM=BN=64, BK=16, 256 threads, 4x4 per-thread tile.
// ---------------------------------------------------------------------------
#define BM 64
#define BN 64
#define BK 16

__global__ __launch_bounds__(256) void gemm_bias_relu_kernel(
    const float* __restrict__ A, const float* __restrict__ B,
    const float* __restrict__ bias, float* __restrict__ Cmat,
    int M, int N, int K, int relu)
{
    __shared__ float As[BK][BM + 4];
    __shared__ float Bs[BK][BN];

    const int tid = threadIdx.x;
    const int m0 = blockIdx.y * BM;
    const int n0 = blockIdx.x * BN;

    const int arow = tid >> 2;          // 0..63
    const int acol = (tid & 3) * 4;     // 0,4,8,12
    const int brow = tid >> 4;          // 0..15
    const int bcol = (tid & 15) * 4;    // 0..60

    const int ty = tid >> 4;            // 0..15 (row group of 4)
    const int tx = tid & 15;            // 0..15 (col group of 4)

    float acc[4][4] = {};

    for (int k0 = 0; k0 < K; k0 += BK) {
        float4 av = *(const float4*)&A[(size_t)(m0 + arow) * K + k0 + acol];
        As[acol + 0][arow] = av.x;
        As[acol + 1][arow] = av.y;
        As[acol + 2][arow] = av.z;
        As[acol + 3][arow] = av.w;
        float4 bv = *(const float4*)&B[(size_t)(k0 + brow) * N + n0 + bcol];
        *(float4*)&Bs[brow][bcol] = bv;
        __syncthreads();

        #pragma unroll
        for (int k = 0; k < BK; k++) {
            float a[4], b[4];
            #pragma unroll
            for (int i = 0; i < 4; i++) a[i] = As[k][ty * 4 + i];
            #pragma unroll
            for (int j = 0; j < 4; j++) b[j] = Bs[k][tx * 4 + j];
            #pragma unroll
            for (int i = 0; i < 4; i++)
                #pragma unroll
                for (int j = 0; j < 4; j++)
                    acc[i][j] = fmaf(a[i], b[j], acc[i][j]);
        }
        __syncthreads();
    }

    #pragma unroll
    for (int i = 0; i < 4; i++) {
        const int m = m0 + ty * 4 + i;
        #pragma unroll
        for (int j = 0; j < 4; j++) {
            const int nn = n0 + tx * 4 + j;
            float v = acc[i][j] + bias[nn];
            if (relu) v = fmaxf(v, 0.0f);
            Cmat[(size_t)m * N + nn] = v;
        }
    }
}

// ---------------------------------------------------------------------------
// Heads: per-roi block, fc7 row staged in shared, one thread per output.
// out layout: [256*84 loc][256*21 cls]
// ---------------------------------------------------------------------------
__global__ __launch_bounds__(128) void head_kernel(
    const float* __restrict__ fc7,
    const float* __restrict__ Wloc, const float* __restrict__ bloc,
    const float* __restrict__ Wcls, const float* __restrict__ bcls,
    float* __restrict__ out)
{
    __shared__ float xr[DH];
    const int n = blockIdx.x;
    for (int k = threadIdx.x; k < DH; k += blockDim.x)
        xr[k] = fc7[(size_t)n * DH + k];
    __syncthreads();

    const int j = threadIdx.x;
    if (j < NLOC) {
        float acc = bloc[j];
        #pragma unroll 8
        for (int k = 0; k < DH; k++)
            acc = fmaf(xr[k], Wloc[(size_t)k * NLOC + j], acc);
        out[(size_t)n * NLOC + j] = acc;
    } else if (j < NLOC + NCLS) {
        const int jc = j - NLOC;
        float acc = bcls[jc];
        #pragma unroll 8
        for (int k = 0; k < DH; k++)
            acc = fmaf(xr[k], Wcls[(size_t)k * NCLS + jc], acc);
        out[(size_t)N_ROI * NLOC + (size_t)n * NCLS + jc] = acc;
    }
}

// ---------------------------------------------------------------------------
extern "C" void kernel_launch(void* const* d_in, const int* in_sizes, int n_in,
                              void* d_out, int out_size)
{
    const float* f3   = (const float*)d_in[0];
    const float* f4   = (const float*)d_in[1];
    const float* f5   = (const float*)d_in[2];
    const float* rois = (const float*)d_in[3];
    const float* Wfc6 = (const float*)d_in[4];
    const float* bfc6 = (const float*)d_in[5];
    const float* Wfc7 = (const float*)d_in[6];
    const float* bfc7 = (const float*)d_in[7];
    const float* Wloc = (const float*)d_in[8];
    const float* bloc = (const float*)d_in[9];
    const float* Wcls = (const float*)d_in[10];
    const float* bcls = (const float*)d_in[11];
    float* out = (float*)d_out;

    float *pooled, *fc6, *fc7;
    cudaGetSymbolAddress((void**)&pooled, g_pooled);
    cudaGetSymbolAddress((void**)&fc6, g_fc6);
    cudaGetSymbolAddress((void**)&fc7, g_fc7);

    // 1) roi_pool
    roi_pool_kernel<<<N_ROI, CCH>>>(f3, f4, f5, rois, pooled);

    // 2) fc6 = relu(pooled @ Wfc6 + b)  (M=256, K=12544, N=4096)
    gemm_bias_relu_kernel<<<dim3(DH / BN, N_ROI / BM), 256>>>(
        pooled, Wfc6, bfc6, fc6, N_ROI, DH, DIN, 1);

    // 3) fc7 = relu(fc6 @ Wfc7 + b)    (M=256, K=4096, N=4096)
    gemm_bias_relu_kernel<<<dim3(DH / BN, N_ROI / BM), 256>>>(
        fc6, Wfc7, bfc7, fc7, N_ROI, DH, DH, 1);

    // 4) heads
    head_kernel<<<N_ROI, 128>>>(fc7, Wloc, bloc, Wcls, bcls, out);
}

// round 3
// speedup vs baseline: 1.4751x; 1.4751x over previous
#include <cuda_runtime.h>
#include <math.h>
#include <stdint.h>

#define N_ROI 256
#define CCH   256
#define DIN   12544   // 256*49
#define DH    4096
#define NLOC  84
#define NCLS  21
#define NHEAD 105

// Scratch (no allocations allowed in kernel_launch)
__device__ float g_pooled[N_ROI * DIN];
__device__ float g_fc6[N_ROI * DH];
__device__ float g_fc7[N_ROI * DH];

// ---------------------------------------------------------------------------
// RoI max-pool over FPN levels. One block per roi, one thread per channel.
// ---------------------------------------------------------------------------
__global__ void roi_pool_kernel(const float* __restrict__ f3,
                                const float* __restrict__ f4,
                                const float* __restrict__ f5,
                                const float* __restrict__ rois,
                                float* __restrict__ pooled)
{
    const int n = blockIdx.x;
    const int c = threadIdx.x;

    const float y1 = rois[n * 4 + 0];
    const float x1 = rois[n * 4 + 1];
    const float y2 = rois[n * 4 + 2];
    const float x2 = rois[n * 4 + 3];

    const float Hr = y2 - y1;
    const float Wr = x2 - x1;
    float lv = rintf(logf(sqrtf(Hr * Wr) / 224.0f) + 5.0f);
    lv = fminf(fmaxf(lv, 3.0f), 5.0f);
    const int l = (int)lv - 3;

    const float scale = (l == 0) ? 0.125f : (l == 1 ? 0.0625f : 0.03125f);
    const int   hw    = (l == 0) ? 100    : (l == 1 ? 50      : 25);
    const float* fmap = (l == 0) ? f3     : (l == 1 ? f4      : f5);
    fmap += (size_t)c * hw * hw;

    const float ys = floorf(y1 * scale + 0.5f);
    const float xs = floorf(x1 * scale + 0.5f);
    const float ye = floorf(y2 * scale + 0.5f);
    const float xe = floorf(x2 * scale + 0.5f);
    const float bh = fmaxf(ye - ys + 1.0f, 1.0f) * (1.0f / 7.0f);
    const float bw = fmaxf(xe - xs + 1.0f, 1.0f) * (1.0f / 7.0f);

    float* orow = pooled + (size_t)n * DIN + (size_t)c * 49;

    #pragma unroll
    for (int ph = 0; ph < 7; ph++) {
        int h0 = (int)fminf(fmaxf(floorf((float)ph * bh) + ys, 0.0f), (float)hw);
        int h1 = (int)fminf(fmaxf(ceilf((float)(ph + 1) * bh) + ys, 0.0f), (float)hw);
        #pragma unroll
        for (int pw = 0; pw < 7; pw++) {
            int w0 = (int)fminf(fmaxf(floorf((float)pw * bw) + xs, 0.0f), (float)hw);
            int w1 = (int)fminf(fmaxf(ceilf((float)(pw + 1) * bw) + xs, 0.0f), (float)hw);
            float m;
            if (h1 <= h0 || w1 <= w0) {
                m = 0.0f;
            } else {
                m = -INFINITY;
                for (int r = h0; r < h1; r++) {
                    const float* rowp = fmap + r * hw;
                    for (int q = w0; q < w1; q++)
                        m = fmaxf(m, rowp[q]);
                }
            }
            orow[ph * 7 + pw] = m;
        }
    }
}

// ---------------------------------------------------------------------------
// TF32 mma.sync GEMM: C[M,N] = relu?(A[M,K] @ B[K,N] + bias)
//   Block tile 64x128x32, 8 warps (2m x 4n), warp tile 32x32 (2x4 m16n8k8).
//   Double-buffered smem, register-prefetch pipeline, cvt.rna tf32 on STS.
//   A smem [64][36]  (4*row+col mod 32 -> conflict-free A-frag LDS)
//   B smem [32][136] (8*k+n   mod 32 -> conflict-free B-frag LDS)
// ---------------------------------------------------------------------------
#define BM 64
#define BN 128
#define BK 32
#define TPB 256
#define ASTR 36
#define BSTR 136
#define A_STAGE (BM * ASTR)          // 2304 floats
#define B_STAGE (BK * BSTR)          // 4352 floats
#define SMEM_FLOATS (2 * (A_STAGE + B_STAGE))   // 13312 floats = 53248 B

static __device__ __forceinline__ float tf32r(float x) {
    float r;
    asm("cvt.rna.tf32.f32 %0, %1;" : "=f"(r) : "f"(x));
    return r;
}

static __device__ __forceinline__ void mma16n8k8(
    float& c0, float& c1, float& c2, float& c3,
    uint32_t a0, uint32_t a1, uint32_t a2, uint32_t a3,
    uint32_t b0, uint32_t b1)
{
    asm volatile(
        "mma.sync.aligned.m16n8k8.row.col.f32.tf32.tf32.f32 "
        "{%0,%1,%2,%3},{%4,%5,%6,%7},{%8,%9},{%0,%1,%2,%3};"
        : "+f"(c0), "+f"(c1), "+f"(c2), "+f"(c3)
        : "r"(a0), "r"(a1), "r"(a2), "r"(a3), "r"(b0), "r"(b1));
}

__global__ __launch_bounds__(TPB, 1) void gemm_tf32_kernel(
    const float* __restrict__ A, const float* __restrict__ B,
    const float* __restrict__ bias, float* __restrict__ C,
    int M, int N, int K, int relu)
{
    extern __shared__ float sm[];
    float* As = sm;                       // [2][BM][ASTR]
    float* Bs = sm + 2 * A_STAGE;         // [2][BK][BSTR]

    const int tid  = threadIdx.x;
    const int wid  = tid >> 5;
    const int lane = tid & 31;
    const int gid  = lane >> 2;   // groupID 0..7
    const int tig  = lane & 3;    // thread-in-group 0..3

    const int wm = wid & 1;       // warp m 0..1
    const int wn = wid >> 1;      // warp n 0..3

    const int m0 = blockIdx.y * BM;
    const int n0 = blockIdx.x * BN;

    // global-load indices
    const int arow0 = tid >> 3;           // + p*32 ; 2 passes
    const int acol  = (tid & 7) * 4;
    const int brow0 = tid >> 5;           // + p*8  ; 4 passes
    const int bcol  = (tid & 31) * 4;

    float acc[2][4][4];
    #pragma unroll
    for (int i = 0; i < 2; i++)
        #pragma unroll
        for (int j = 0; j < 4; j++)
            #pragma unroll
            for (int q = 0; q < 4; q++) acc[i][j][q] = 0.0f;

    const int nkt = K / BK;

    // prologue: fill stage 0
    {
        #pragma unroll
        for (int p = 0; p < 2; p++) {
            const int r = arow0 + p * 32;
            float4 v = *(const float4*)(A + (size_t)(m0 + r) * K + acol);
            float* d = As + r * ASTR + acol;
            d[0] = tf32r(v.x); d[1] = tf32r(v.y); d[2] = tf32r(v.z); d[3] = tf32r(v.w);
        }
        #pragma unroll
        for (int p = 0; p < 4; p++) {
            const int r = brow0 + p * 8;
            float4 v = *(const float4*)(B + (size_t)r * N + n0 + bcol);
            float* d = Bs + r * BSTR + bcol;
            d[0] = tf32r(v.x); d[1] = tf32r(v.y); d[2] = tf32r(v.z); d[3] = tf32r(v.w);
        }
    }
    __syncthreads();

    int buf = 0;
    for (int kt = 0; kt < nkt; kt++) {
        float4 pa[2], pb[4];
        const bool more = (kt + 1) < nkt;
        if (more) {
            const int k0 = (kt + 1) * BK;
            #pragma unroll
            for (int p = 0; p < 2; p++)
                pa[p] = *(const float4*)(A + (size_t)(m0 + arow0 + p * 32) * K + k0 + acol);
            #pragma unroll
            for (int p = 0; p < 4; p++)
                pb[p] = *(const float4*)(B + (size_t)(k0 + brow0 + p * 8) * N + n0 + bcol);
        }

        // compute current stage
        const float* Ab = As + buf * A_STAGE;
        const float* Bb = Bs + buf * B_STAGE;
        const int ra = wm * 32 + gid;
        const int nb = wn * 32 + gid;
        #pragma unroll
        for (int ks = 0; ks < 4; ks++) {
            const int ca = ks * 8 + tig;
            uint32_t af[2][4];
            #pragma unroll
            for (int tm = 0; tm < 2; tm++) {
                const float* ap = Ab + (ra + tm * 16) * ASTR + ca;
                af[tm][0] = __float_as_uint(ap[0]);
                af[tm][1] = __float_as_uint(ap[8 * ASTR]);
                af[tm][2] = __float_as_uint(ap[4]);
                af[tm][3] = __float_as_uint(ap[8 * ASTR + 4]);
            }
            uint32_t bf[4][2];
            #pragma unroll
            for (int tn = 0; tn < 4; tn++) {
                const float* bp = Bb + ca * BSTR + nb + tn * 8;
                bf[tn][0] = __float_as_uint(bp[0]);
                bf[tn][1] = __float_as_uint(bp[4 * BSTR]);
            }
            #pragma unroll
            for (int tm = 0; tm < 2; tm++)
                #pragma unroll
                for (int tn = 0; tn < 4; tn++)
                    mma16n8k8(acc[tm][tn][0], acc[tm][tn][1], acc[tm][tn][2], acc[tm][tn][3],
                              af[tm][0], af[tm][1], af[tm][2], af[tm][3],
                              bf[tn][0], bf[tn][1]);
        }

        if (more) {
            float* Ad = As + (buf ^ 1) * A_STAGE;
            float* Bd = Bs + (buf ^ 1) * B_STAGE;
            #pragma unroll
            for (int p = 0; p < 2; p++) {
                float* d = Ad + (arow0 + p * 32) * ASTR + acol;
                d[0] = tf32r(pa[p].x); d[1] = tf32r(pa[p].y);
                d[2] = tf32r(pa[p].z); d[3] = tf32r(pa[p].w);
            }
            #pragma unroll
            for (int p = 0; p < 4; p++) {
                float* d = Bd + (brow0 + p * 8) * BSTR + bcol;
                d[0] = tf32r(pb[p].x); d[1] = tf32r(pb[p].y);
                d[2] = tf32r(pb[p].z); d[3] = tf32r(pb[p].w);
            }
        }
        __syncthreads();
        buf ^= 1;
    }

    // epilogue: c0 (row=gid, col=2*tig), c1 (+1), c2 (row+8), c3 (row+8,+1)
    #pragma unroll
    for (int tm = 0; tm < 2; tm++) {
        const int rbase = m0 + wm * 32 + tm * 16 + gid;
        #pragma unroll
        for (int tn = 0; tn < 4; tn++) {
            const int cb = n0 + wn * 32 + tn * 8 + tig * 2;
            const float b0 = bias[cb], b1 = bias[cb + 1];
            float v0 = acc[tm][tn][0] + b0, v1 = acc[tm][tn][1] + b1;
            float v2 = acc[tm][tn][2] + b0, v3 = acc[tm][tn][3] + b1;
            if (relu) {
                v0 = fmaxf(v0, 0.0f); v1 = fmaxf(v1, 0.0f);
                v2 = fmaxf(v2, 0.0f); v3 = fmaxf(v3, 0.0f);
            }
            *(float2*)(C + (size_t)rbase * N + cb)       = make_float2(v0, v1);
            *(float2*)(C + (size_t)(rbase + 8) * N + cb) = make_float2(v2, v3);
        }
    }
}

// ---------------------------------------------------------------------------
// Heads: 2 rois per block, weights staged coalesced through smem in 32-k chunks.
// out layout: [256*84 loc][256*21 cls]
// ---------------------------------------------------------------------------
__global__ __launch_bounds__(128) void head_kernel(
    const float* __restrict__ fc7,
    const float* __restrict__ Wloc, const float* __restrict__ bloc,
    const float* __restrict__ Wcls, const float* __restrict__ bcls,
    float* __restrict__ out)
{
    __shared__ float xs[2][DH];              // 32 KB
    __shared__ float ws[32][NHEAD + 3];      // padded
    const int tid = threadIdx.x;
    const int n0r = blockIdx.x * 2;

    for (int k = tid; k < DH; k += 128) {
        xs[0][k] = fc7[(size_t)n0r * DH + k];
        xs[1][k] = fc7[(size_t)(n0r + 1) * DH + k];
    }
    float acc0 = 0.0f, acc1 = 0.0f;

    for (int k0 = 0; k0 < DH; k0 += 32) {
        __syncthreads();
        for (int idx = tid; idx < 32 * NHEAD; idx += 128) {
            const int kk = idx / NHEAD;
            const int j  = idx - kk * NHEAD;
            ws[kk][j] = (j < NLOC)
                ? Wloc[(size_t)(k0 + kk) * NLOC + j]
                : Wcls[(size_t)(k0 + kk) * NCLS + (j - NLOC)];
        }
        __syncthreads();
        if (tid < NHEAD) {
            #pragma unroll 8
            for (int kk = 0; kk < 32; kk++) {
                const float w = ws[kk][tid];
                acc0 = fmaf(xs[0][k0 + kk], w, acc0);
                acc1 = fmaf(xs[1][k0 + kk], w, acc1);
            }
        }
    }

    if (tid < NLOC) {
        const float b = bloc[tid];
        out[(size_t)n0r * NLOC + tid]       = acc0 + b;
        out[(size_t)(n0r + 1) * NLOC + tid] = acc1 + b;
    } else if (tid < NHEAD) {
        const int jc = tid - NLOC;
        const float b = bcls[jc];
        out[(size_t)N_ROI * NLOC + (size_t)n0r * NCLS + jc]       = acc0 + b;
        out[(size_t)N_ROI * NLOC + (size_t)(n0r + 1) * NCLS + jc] = acc1 + b;
    }
}

// ---------------------------------------------------------------------------
extern "C" void kernel_launch(void* const* d_in, const int* in_sizes, int n_in,
                              void* d_out, int out_size)
{
    const float* f3   = (const float*)d_in[0];
    const float* f4   = (const float*)d_in[1];
    const float* f5   = (const float*)d_in[2];
    const float* rois = (const float*)d_in[3];
    const float* Wfc6 = (const float*)d_in[4];
    const float* bfc6 = (const float*)d_in[5];
    const float* Wfc7 = (const float*)d_in[6];
    const float* bfc7 = (const float*)d_in[7];
    const float* Wloc = (const float*)d_in[8];
    const float* bloc = (const float*)d_in[9];
    const float* Wcls = (const float*)d_in[10];
    const float* bcls = (const float*)d_in[11];
    float* out = (float*)d_out;

    float *pooled, *fc6, *fc7;
    cudaGetSymbolAddress((void**)&pooled, g_pooled);
    cudaGetSymbolAddress((void**)&fc6, g_fc6);
    cudaGetSymbolAddress((void**)&fc7, g_fc7);

    const int smemB = SMEM_FLOATS * (int)sizeof(float);
    cudaFuncSetAttribute(gemm_tf32_kernel,
                         cudaFuncAttributeMaxDynamicSharedMemorySize, smemB);

    // 1) roi_pool
    roi_pool_kernel<<<N_ROI, CCH>>>(f3, f4, f5, rois, pooled);

    // 2) fc6 = relu(pooled @ Wfc6 + b)  (M=256, K=12544, N=4096)
    gemm_tf32_kernel<<<dim3(DH / BN, N_ROI / BM), TPB, smemB>>>(
        pooled, Wfc6, bfc6, fc6, N_ROI, DH, DIN, 1);

    // 3) fc7 = relu(fc6 @ Wfc7 + b)    (M=256, K=4096, N=4096)
    gemm_tf32_kernel<<<dim3(DH / BN, N_ROI / BM), TPB, smemB>>>(
        fc6, Wfc7, bfc7, fc7, N_ROI, DH, DH, 1);

    // 4) heads
    head_kernel<<<N_ROI / 2, 128>>>(fc7, Wloc, bloc, Wcls, bcls, out);
}

// round 4
// speedup vs baseline: 2.2428x; 1.5204x over previous
#include <cuda_runtime.h>
#include <math.h>
#include <stdint.h>

#define N_ROI 256
#define CCH   256
#define DIN   12544   // 256*49
#define DH    4096
#define NLOC  84
#define NCLS  21
#define NHEAD 105
#define NHPAD 128

// Scratch (no allocations allowed in kernel_launch)
__device__ float g_pooled[N_ROI * DIN];
__device__ float g_fc6[N_ROI * DH];
__device__ float g_fc7[N_ROI * DH];
__device__ float g_whead[DH * NHPAD];
__device__ float g_bhead[NHPAD];
__device__ float g_head[N_ROI * NHPAD];

// ---------------------------------------------------------------------------
// RoI max-pool over FPN levels. One block per roi, one thread per channel.
// ---------------------------------------------------------------------------
__global__ void roi_pool_kernel(const float* __restrict__ f3,
                                const float* __restrict__ f4,
                                const float* __restrict__ f5,
                                const float* __restrict__ rois,
                                float* __restrict__ pooled)
{
    const int n = blockIdx.x;
    const int c = threadIdx.x;

    const float y1 = rois[n * 4 + 0];
    const float x1 = rois[n * 4 + 1];
    const float y2 = rois[n * 4 + 2];
    const float x2 = rois[n * 4 + 3];

    const float Hr = y2 - y1;
    const float Wr = x2 - x1;
    float lv = rintf(logf(sqrtf(Hr * Wr) / 224.0f) + 5.0f);
    lv = fminf(fmaxf(lv, 3.0f), 5.0f);
    const int l = (int)lv - 3;

    const float scale = (l == 0) ? 0.125f : (l == 1 ? 0.0625f : 0.03125f);
    const int   hw    = (l == 0) ? 100    : (l == 1 ? 50      : 25);
    const float* fmap = (l == 0) ? f3     : (l == 1 ? f4      : f5);
    fmap += (size_t)c * hw * hw;

    const float ys = floorf(y1 * scale + 0.5f);
    const float xs = floorf(x1 * scale + 0.5f);
    const float ye = floorf(y2 * scale + 0.5f);
    const float xe = floorf(x2 * scale + 0.5f);
    const float bh = fmaxf(ye - ys + 1.0f, 1.0f) * (1.0f / 7.0f);
    const float bw = fmaxf(xe - xs + 1.0f, 1.0f) * (1.0f / 7.0f);

    float* orow = pooled + (size_t)n * DIN + (size_t)c * 49;

    #pragma unroll
    for (int ph = 0; ph < 7; ph++) {
        int h0 = (int)fminf(fmaxf(floorf((float)ph * bh) + ys, 0.0f), (float)hw);
        int h1 = (int)fminf(fmaxf(ceilf((float)(ph + 1) * bh) + ys, 0.0f), (float)hw);
        #pragma unroll
        for (int pw = 0; pw < 7; pw++) {
            int w0 = (int)fminf(fmaxf(floorf((float)pw * bw) + xs, 0.0f), (float)hw);
            int w1 = (int)fminf(fmaxf(ceilf((float)(pw + 1) * bw) + xs, 0.0f), (float)hw);
            float m;
            if (h1 <= h0 || w1 <= w0) {
                m = 0.0f;
            } else {
                m = -INFINITY;
                for (int r = h0; r < h1; r++) {
                    const float* rowp = fmap + r * hw;
                    for (int q = w0; q < w1; q++)
                        m = fmaxf(m, rowp[q]);
                }
            }
            orow[ph * 7 + pw] = m;
        }
    }
}

// ---------------------------------------------------------------------------
// TF32 mma.sync GEMM: C[M,N] = relu?(A[M,K] @ B[K,N] + bias)
//   Block tile 64x128x32, 8 warps (2m x 4n), warp tile 32x32 (2x4 m16n8k8).
//   Double-buffered smem, register-prefetch of globals AND fragments,
//   cvt.rna tf32 on STS.
// ---------------------------------------------------------------------------
#define BM 64
#define BN 128
#define BK 32
#define TPB 256
#define ASTR 36
#define BSTR 136
#define A_STAGE (BM * ASTR)          // 2304 floats
#define B_STAGE (BK * BSTR)          // 4352 floats
#define SMEM_FLOATS (2 * (A_STAGE + B_STAGE))   // 13312 floats = 53248 B

static __device__ __forceinline__ float tf32r(float x) {
    float r;
    asm("cvt.rna.tf32.f32 %0, %1;" : "=f"(r) : "f"(x));
    return r;
}

static __device__ __forceinline__ void mma16n8k8(
    float& c0, float& c1, float& c2, float& c3,
    uint32_t a0, uint32_t a1, uint32_t a2, uint32_t a3,
    uint32_t b0, uint32_t b1)
{
    asm volatile(
        "mma.sync.aligned.m16n8k8.row.col.f32.tf32.tf32.f32 "
        "{%0,%1,%2,%3},{%4,%5,%6,%7},{%8,%9},{%0,%1,%2,%3};"
        : "+f"(c0), "+f"(c1), "+f"(c2), "+f"(c3)
        : "r"(a0), "r"(a1), "r"(a2), "r"(a3), "r"(b0), "r"(b1));
}

__global__ __launch_bounds__(TPB, 1) void gemm_tf32_kernel(
    const float* __restrict__ A, const float* __restrict__ B,
    const float* __restrict__ bias, float* __restrict__ C,
    int M, int N, int K, int relu)
{
    extern __shared__ float sm[];
    float* As = sm;                       // [2][BM][ASTR]
    float* Bs = sm + 2 * A_STAGE;         // [2][BK][BSTR]

    const int tid  = threadIdx.x;
    const int wid  = tid >> 5;
    const int lane = tid & 31;
    const int gid  = lane >> 2;   // groupID 0..7
    const int tig  = lane & 3;    // thread-in-group 0..3

    const int wm = wid & 1;       // warp m 0..1
    const int wn = wid >> 1;      // warp n 0..3

    const int m0 = blockIdx.y * BM;
    const int n0 = blockIdx.x * BN;

    // global-load indices
    const int arow0 = tid >> 3;           // + p*32 ; 2 passes
    const int acol  = (tid & 7) * 4;
    const int brow0 = tid >> 5;           // + p*8  ; 4 passes
    const int bcol  = (tid & 31) * 4;

    float acc[2][4][4];
    #pragma unroll
    for (int i = 0; i < 2; i++)
        #pragma unroll
        for (int j = 0; j < 4; j++)
            #pragma unroll
            for (int q = 0; q < 4; q++) acc[i][j][q] = 0.0f;

    const int nkt = K / BK;

    // prologue: fill stage 0
    {
        #pragma unroll
        for (int p = 0; p < 2; p++) {
            const int r = arow0 + p * 32;
            float4 v = *(const float4*)(A + (size_t)(m0 + r) * K + acol);
            float* d = As + r * ASTR + acol;
            d[0] = tf32r(v.x); d[1] = tf32r(v.y); d[2] = tf32r(v.z); d[3] = tf32r(v.w);
        }
        #pragma unroll
        for (int p = 0; p < 4; p++) {
            const int r = brow0 + p * 8;
            float4 v = *(const float4*)(B + (size_t)r * N + n0 + bcol);
            float* d = Bs + r * BSTR + bcol;
            d[0] = tf32r(v.x); d[1] = tf32r(v.y); d[2] = tf32r(v.z); d[3] = tf32r(v.w);
        }
    }
    __syncthreads();

    const int ra = wm * 32 + gid;
    const int nb = wn * 32 + gid;

    int buf = 0;
    for (int kt = 0; kt < nkt; kt++) {
        float4 pa[2], pb[4];
        const bool more = (kt + 1) < nkt;
        if (more) {
            const int k0 = (kt + 1) * BK;
            #pragma unroll
            for (int p = 0; p < 2; p++)
                pa[p] = *(const float4*)(A + (size_t)(m0 + arow0 + p * 32) * K + k0 + acol);
            #pragma unroll
            for (int p = 0; p < 4; p++)
                pb[p] = *(const float4*)(B + (size_t)(k0 + brow0 + p * 8) * N + n0 + bcol);
        }

        // compute current stage with register fragment double-buffering
        const float* Ab = As + buf * A_STAGE;
        const float* Bb = Bs + buf * B_STAGE;

        uint32_t af[2][2][4];   // [pipe][tm][frag]
        uint32_t bf[2][4][2];   // [pipe][tn][frag]

        // load ks = 0 fragments
        {
            const int ca = tig;
            #pragma unroll
            for (int tm = 0; tm < 2; tm++) {
                const float* ap = Ab + (ra + tm * 16) * ASTR + ca;
                af[0][tm][0] = __float_as_uint(ap[0]);
                af[0][tm][1] = __float_as_uint(ap[8 * ASTR]);
                af[0][tm][2] = __float_as_uint(ap[4]);
                af[0][tm][3] = __float_as_uint(ap[8 * ASTR + 4]);
            }
            #pragma unroll
            for (int tn = 0; tn < 4; tn++) {
                const float* bp = Bb + ca * BSTR + nb + tn * 8;
                bf[0][tn][0] = __float_as_uint(bp[0]);
                bf[0][tn][1] = __float_as_uint(bp[4 * BSTR]);
            }
        }

        #pragma unroll
        for (int ks = 0; ks < 4; ks++) {
            const int cur = ks & 1;
            const int nxt = cur ^ 1;
            if (ks < 3) {
                const int ca = (ks + 1) * 8 + tig;
                #pragma unroll
                for (int tm = 0; tm < 2; tm++) {
                    const float* ap = Ab + (ra + tm * 16) * ASTR + ca;
                    af[nxt][tm][0] = __float_as_uint(ap[0]);
                    af[nxt][tm][1] = __float_as_uint(ap[8 * ASTR]);
                    af[nxt][tm][2] = __float_as_uint(ap[4]);
                    af[nxt][tm][3] = __float_as_uint(ap[8 * ASTR + 4]);
                }
                #pragma unroll
                for (int tn = 0; tn < 4; tn++) {
                    const float* bp = Bb + ca * BSTR + nb + tn * 8;
                    bf[nxt][tn][0] = __float_as_uint(bp[0]);
                    bf[nxt][tn][1] = __float_as_uint(bp[4 * BSTR]);
                }
            }
            #pragma unroll
            for (int tm = 0; tm < 2; tm++)
                #pragma unroll
                for (int tn = 0; tn < 4; tn++)
                    mma16n8k8(acc[tm][tn][0], acc[tm][tn][1], acc[tm][tn][2], acc[tm][tn][3],
                              af[cur][tm][0], af[cur][tm][1], af[cur][tm][2], af[cur][tm][3],
                              bf[cur][tn][0], bf[cur][tn][1]);
        }

        if (more) {
            float* Ad = As + (buf ^ 1) * A_STAGE;
            float* Bd = Bs + (buf ^ 1) * B_STAGE;
            #pragma unroll
            for (int p = 0; p < 2; p++) {
                float* d = Ad + (arow0 + p * 32) * ASTR + acol;
                d[0] = tf32r(pa[p].x); d[1] = tf32r(pa[p].y);
                d[2] = tf32r(pa[p].z); d[3] = tf32r(pa[p].w);
            }
            #pragma unroll
            for (int p = 0; p < 4; p++) {
                float* d = Bd + (brow0 + p * 8) * BSTR + bcol;
                d[0] = tf32r(pb[p].x); d[1] = tf32r(pb[p].y);
                d[2] = tf32r(pb[p].z); d[3] = tf32r(pb[p].w);
            }
        }
        __syncthreads();
        buf ^= 1;
    }

    // epilogue
    #pragma unroll
    for (int tm = 0; tm < 2; tm++) {
        const int rbase = m0 + wm * 32 + tm * 16 + gid;
        #pragma unroll
        for (int tn = 0; tn < 4; tn++) {
            const int cb = n0 + wn * 32 + tn * 8 + tig * 2;
            const float b0 = bias[cb], b1 = bias[cb + 1];
            float v0 = acc[tm][tn][0] + b0, v1 = acc[tm][tn][1] + b1;
            float v2 = acc[tm][tn][2] + b0, v3 = acc[tm][tn][3] + b1;
            if (relu) {
                v0 = fmaxf(v0, 0.0f); v1 = fmaxf(v1, 0.0f);
                v2 = fmaxf(v2, 0.0f); v3 = fmaxf(v3, 0.0f);
            }
            *(float2*)(C + (size_t)rbase * N + cb)       = make_float2(v0, v1);
            *(float2*)(C + (size_t)(rbase + 8) * N + cb) = make_float2(v2, v3);
        }
    }
}

// ---------------------------------------------------------------------------
// Pack head weights/bias: Whead[k][0:84]=Wloc, [84:105]=Wcls, [105:128]=0.
// ---------------------------------------------------------------------------
__global__ __launch_bounds__(256) void pack_head_kernel(
    const float* __restrict__ Wloc, const float* __restrict__ Wcls,
    const float* __restrict__ bloc, const float* __restrict__ bcls,
    float* __restrict__ Wh, float* __restrict__ bh)
{
    const int idx = blockIdx.x * 256 + threadIdx.x;   // DH*NHPAD total
    const int k = idx >> 7;
    const int j = idx & 127;
    float v = 0.0f;
    if (j < NLOC)       v = Wloc[(size_t)k * NLOC + j];
    else if (j < NHEAD) v = Wcls[(size_t)k * NCLS + (j - NLOC)];
    Wh[idx] = v;
    if (idx < NHPAD) {
        float b = 0.0f;
        if (idx < NLOC)       b = bloc[idx];
        else if (idx < NHEAD) b = bcls[idx - NLOC];
        bh[idx] = b;
    }
}

// ---------------------------------------------------------------------------
// Scatter head GEMM result into output layout [256*84 loc][256*21 cls].
// ---------------------------------------------------------------------------
__global__ __launch_bounds__(128) void scatter_head_kernel(
    const float* __restrict__ h, float* __restrict__ out)
{
    const int n = blockIdx.x;
    const int j = threadIdx.x;
    if (j < NLOC) {
        out[(size_t)n * NLOC + j] = h[(size_t)n * NHPAD + j];
    } else if (j < NHEAD) {
        out[(size_t)N_ROI * NLOC + (size_t)n * NCLS + (j - NLOC)] =
            h[(size_t)n * NHPAD + j];
    }
}

// ---------------------------------------------------------------------------
extern "C" void kernel_launch(void* const* d_in, const int* in_sizes, int n_in,
                              void* d_out, int out_size)
{
    const float* f3   = (const float*)d_in[0];
    const float* f4   = (const float*)d_in[1];
    const float* f5   = (const float*)d_in[2];
    const float* rois = (const float*)d_in[3];
    const float* Wfc6 = (const float*)d_in[4];
    const float* bfc6 = (const float*)d_in[5];
    const float* Wfc7 = (const float*)d_in[6];
    const float* bfc7 = (const float*)d_in[7];
    const float* Wloc = (const float*)d_in[8];
    const float* bloc = (const float*)d_in[9];
    const float* Wcls = (const float*)d_in[10];
    const float* bcls = (const float*)d_in[11];
    float* out = (float*)d_out;

    float *pooled, *fc6, *fc7, *whead, *bhead, *head;
    cudaGetSymbolAddress((void**)&pooled, g_pooled);
    cudaGetSymbolAddress((void**)&fc6, g_fc6);
    cudaGetSymbolAddress((void**)&fc7, g_fc7);
    cudaGetSymbolAddress((void**)&whead, g_whead);
    cudaGetSymbolAddress((void**)&bhead, g_bhead);
    cudaGetSymbolAddress((void**)&head, g_head);

    const int smemB = SMEM_FLOATS * (int)sizeof(float);
    cudaFuncSetAttribute(gemm_tf32_kernel,
                         cudaFuncAttributeMaxDynamicSharedMemorySize, smemB);

    // 0) pack head weights (overlaps nothing but is ~2us)
    pack_head_kernel<<<(DH * NHPAD) / 256, 256>>>(Wloc, Wcls, bloc, bcls, whead, bhead);

    // 1) roi_pool
    roi_pool_kernel<<<N_ROI, CCH>>>(f3, f4, f5, rois, pooled);

    // 2) fc6 = relu(pooled @ Wfc6 + b)  (M=256, K=12544, N=4096)
    gemm_tf32_kernel<<<dim3(DH / BN, N_ROI / BM), TPB, smemB>>>(
        pooled, Wfc6, bfc6, fc6, N_ROI, DH, DIN, 1);

    // 3) fc7 = relu(fc6 @ Wfc7 + b)    (M=256, K=4096, N=4096)
    gemm_tf32_kernel<<<dim3(DH / BN, N_ROI / BM), TPB, smemB>>>(
        fc6, Wfc7, bfc7, fc7, N_ROI, DH, DH, 1);

    // 4) heads = fc7 @ Whead + bhead   (M=256, K=4096, N=128)
    gemm_tf32_kernel<<<dim3(NHPAD / BN, N_ROI / BM), TPB, smemB>>>(
        fc7, whead, bhead, head, N_ROI, NHPAD, DH, 0);

    // 5) scatter into output layout
    scatter_head_kernel<<<N_ROI, 128>>>(head, out);
}

// round 5
// speedup vs baseline: 4.1197x; 1.8369x over previous
#include <cuda_runtime.h>
#include <math.h>
#include <stdint.h>

#define N_ROI 256
#define CCH   256
#define DIN   12544   // 256*49
#define DH    4096
#define NLOC  84
#define NCLS  21
#define NHEAD 105
#define NHPAD 128
#define HSPLIT 16

// Scratch (no allocations allowed in kernel_launch)
__device__ float g_pooled[N_ROI * DIN];
__device__ float g_fc6[N_ROI * DH];
__device__ float g_fc7[N_ROI * DH];
__device__ float g_whead[DH * NHPAD];
__device__ float g_headpart[HSPLIT * N_ROI * NHPAD];

static __device__ __forceinline__ float tf32r(float x) {
    float r;
    asm("cvt.rna.tf32.f32 %0, %1;" : "=f"(r) : "f"(x));
    return r;
}

// ---------------------------------------------------------------------------
// RoI max-pool over FPN levels. One block per roi, one thread per channel.
// Output pre-rounded to tf32 (feeds the tf32 GEMM A operand).
// ---------------------------------------------------------------------------
__global__ void roi_pool_kernel(const float* __restrict__ f3,
                                const float* __restrict__ f4,
                                const float* __restrict__ f5,
                                const float* __restrict__ rois,
                                float* __restrict__ pooled)
{
    const int n = blockIdx.x;
    const int c = threadIdx.x;

    const float y1 = rois[n * 4 + 0];
    const float x1 = rois[n * 4 + 1];
    const float y2 = rois[n * 4 + 2];
    const float x2 = rois[n * 4 + 3];

    const float Hr = y2 - y1;
    const float Wr = x2 - x1;
    float lv = rintf(logf(sqrtf(Hr * Wr) / 224.0f) + 5.0f);
    lv = fminf(fmaxf(lv, 3.0f), 5.0f);
    const int l = (int)lv - 3;

    const float scale = (l == 0) ? 0.125f : (l == 1 ? 0.0625f : 0.03125f);
    const int   hw    = (l == 0) ? 100    : (l == 1 ? 50      : 25);
    const float* fmap = (l == 0) ? f3     : (l == 1 ? f4      : f5);
    fmap += (size_t)c * hw * hw;

    const float ys = floorf(y1 * scale + 0.5f);
    const float xs = floorf(x1 * scale + 0.5f);
    const float ye = floorf(y2 * scale + 0.5f);
    const float xe = floorf(x2 * scale + 0.5f);
    const float bh = fmaxf(ye - ys + 1.0f, 1.0f) * (1.0f / 7.0f);
    const float bw = fmaxf(xe - xs + 1.0f, 1.0f) * (1.0f / 7.0f);

    float* orow = pooled + (size_t)n * DIN + (size_t)c * 49;

    #pragma unroll
    for (int ph = 0; ph < 7; ph++) {
        int h0 = (int)fminf(fmaxf(floorf((float)ph * bh) + ys, 0.0f), (float)hw);
        int h1 = (int)fminf(fmaxf(ceilf((float)(ph + 1) * bh) + ys, 0.0f), (float)hw);
        #pragma unroll
        for (int pw = 0; pw < 7; pw++) {
            int w0 = (int)fminf(fmaxf(floorf((float)pw * bw) + xs, 0.0f), (float)hw);
            int w1 = (int)fminf(fmaxf(ceilf((float)(pw + 1) * bw) + xs, 0.0f), (float)hw);
            float m;
            if (h1 <= h0 || w1 <= w0) {
                m = 0.0f;
            } else {
                m = -INFINITY;
                for (int r = h0; r < h1; r++) {
                    const float* rowp = fmap + r * hw;
                    for (int q = w0; q < w1; q++)
                        m = fmaxf(m, rowp[q]);
                }
            }
            orow[ph * 7 + pw] = tf32r(m);
        }
    }
}

// ---------------------------------------------------------------------------
// TF32 mma.sync GEMM, cp.async 4-stage pipeline.
//   C[M,N] = mode-dependent epilogue of A[M,lda-slice] @ B[K,N] (+bias)
//   Block tile 64x128x32, 8 warps (2m x 4n), warp tile 32x32 (2x4 m16n8k8).
//   A operand assumed pre-rounded to tf32; B rounded (cvt.rna) on frag load.
//   mode: bit0 = relu, bit1 = round output to tf32, bit2 = partial
//         (no bias, C += blockIdx.z * M * N; K-slice = [z*klen, (z+1)*klen))
// ---------------------------------------------------------------------------
#define BM 64
#define BN 128
#define BK 32
#define TPB 256
#define ASTR 36
#define BSTR 136
#define A_ST (BM * ASTR)                 // 2304 floats
#define B_ST (BK * BSTR)                 // 4352 floats
#define STAGE_FLOATS (A_ST + B_ST)       // 6656 floats = 26624 B
#define STAGES 4
#define SMEM_BYTES (STAGES * STAGE_FLOATS * 4)   // 106496 B

static __device__ __forceinline__ void cpasync16(uint32_t d, const void* s) {
    asm volatile("cp.async.cg.shared.global [%0], [%1], 16;"
                 :: "r"(d), "l"(s));
}

static __device__ __forceinline__ void mma16n8k8(
    float& c0, float& c1, float& c2, float& c3,
    uint32_t a0, uint32_t a1, uint32_t a2, uint32_t a3,
    uint32_t b0, uint32_t b1)
{
    asm volatile(
        "mma.sync.aligned.m16n8k8.row.col.f32.tf32.tf32.f32 "
        "{%0,%1,%2,%3},{%4,%5,%6,%7},{%8,%9},{%0,%1,%2,%3};"
        : "+f"(c0), "+f"(c1), "+f"(c2), "+f"(c3)
        : "r"(a0), "r"(a1), "r"(a2), "r"(a3), "r"(b0), "r"(b1));
}

__global__ __launch_bounds__(TPB, 1) void gemm_tf32_kernel(
    const float* __restrict__ A, const float* __restrict__ B,
    const float* __restrict__ bias, float* __restrict__ C,
    int M, int N, int lda, int ldb, int klen, int mode)
{
    extern __shared__ __align__(16) float sm[];
    uint32_t smbase;
    asm("{ .reg .u64 t; cvta.to.shared.u64 t, %1; cvt.u32.u64 %0, t; }"
        : "=r"(smbase) : "l"(sm));

    const int tid  = threadIdx.x;
    const int wid  = tid >> 5;
    const int lane = tid & 31;
    const int gid  = lane >> 2;
    const int tig  = lane & 3;
    const int wm = wid & 1;
    const int wn = wid >> 1;

    const int m0 = blockIdx.y * BM;
    const int n0 = blockIdx.x * BN;
    const int kstart = blockIdx.z * klen;
    if (mode & 4) C += (size_t)blockIdx.z * M * N;

    // cp.async tile mapping
    const int arow  = tid >> 3;           // 0..31 ; +32 second pass
    const int acol4 = (tid & 7) * 4;
    const int brow  = tid >> 5;           // 0..7  ; +8p, 4 passes
    const int bcol4 = (tid & 31) * 4;

    const float* Agp = A + (size_t)(m0 + arow) * lda + kstart + acol4;
    const float* Bgp = B + (size_t)(kstart + brow) * ldb + n0 + bcol4;
    const uint32_t Asd = smbase + (uint32_t)(arow * ASTR + acol4) * 4u;
    const uint32_t Bsd = smbase + (uint32_t)(A_ST + brow * BSTR + bcol4) * 4u;

    const int nkt = klen / BK;

    float acc[2][4][4];
    #pragma unroll
    for (int i = 0; i < 2; i++)
        #pragma unroll
        for (int j = 0; j < 4; j++)
            #pragma unroll
            for (int q = 0; q < 4; q++) acc[i][j][q] = 0.0f;

    // prologue: stages 0..2
    #pragma unroll
    for (int s = 0; s < STAGES - 1; s++) {
        if (s < nkt) {
            const uint32_t so = (uint32_t)(s * STAGE_FLOATS) * 4u;
            cpasync16(Asd + so, Agp + s * BK);
            cpasync16(Asd + so + 32u * ASTR * 4u, Agp + (size_t)32 * lda + s * BK);
            #pragma unroll
            for (int p = 0; p < 4; p++)
                cpasync16(Bsd + so + (uint32_t)(p * 8 * BSTR) * 4u,
                          Bgp + (size_t)(s * BK + p * 8) * ldb);
        }
        asm volatile("cp.async.commit_group;");
    }

    const int ra = wm * 32 + gid;
    const int nb = wn * 32 + gid;

    for (int kt = 0; kt < nkt; kt++) {
        asm volatile("cp.async.wait_group %0;" :: "n"(STAGES - 2));
        __syncthreads();

        const int stg = kt & (STAGES - 1);
        const float* Ab = sm + stg * STAGE_FLOATS;
        const float* Bb = Ab + A_ST;

        uint32_t af[2][2][4];
        uint32_t bf[2][4][2];

        // ks = 0 fragments (A pre-rounded; B rounded here)
        {
            const int ca = tig;
            #pragma unroll
            for (int tm = 0; tm < 2; tm++) {
                const float* ap = Ab + (ra + tm * 16) * ASTR + ca;
                af[0][tm][0] = __float_as_uint(ap[0]);
                af[0][tm][1] = __float_as_uint(ap[8 * ASTR]);
                af[0][tm][2] = __float_as_uint(ap[4]);
                af[0][tm][3] = __float_as_uint(ap[8 * ASTR + 4]);
            }
            #pragma unroll
            for (int tn = 0; tn < 4; tn++) {
                const float* bp = Bb + ca * BSTR + nb + tn * 8;
                bf[0][tn][0] = __float_as_uint(tf32r(bp[0]));
                bf[0][tn][1] = __float_as_uint(tf32r(bp[4 * BSTR]));
            }
        }

        #pragma unroll
        for (int ks = 0; ks < 4; ks++) {
            const int cur = ks & 1;
            const int nxt = cur ^ 1;
            if (ks < 3) {
                const int ca = (ks + 1) * 8 + tig;
                #pragma unroll
                for (int tm = 0; tm < 2; tm++) {
                    const float* ap = Ab + (ra + tm * 16) * ASTR + ca;
                    af[nxt][tm][0] = __float_as_uint(ap[0]);
                    af[nxt][tm][1] = __float_as_uint(ap[8 * ASTR]);
                    af[nxt][tm][2] = __float_as_uint(ap[4]);
                    af[nxt][tm][3] = __float_as_uint(ap[8 * ASTR + 4]);
                }
                #pragma unroll
                for (int tn = 0; tn < 4; tn++) {
                    const float* bp = Bb + ca * BSTR + nb + tn * 8;
                    bf[nxt][tn][0] = __float_as_uint(tf32r(bp[0]));
                    bf[nxt][tn][1] = __float_as_uint(tf32r(bp[4 * BSTR]));
                }
            }
            #pragma unroll
            for (int tm = 0; tm < 2; tm++)
                #pragma unroll
                for (int tn = 0; tn < 4; tn++)
                    mma16n8k8(acc[tm][tn][0], acc[tm][tn][1], acc[tm][tn][2], acc[tm][tn][3],
                              af[cur][tm][0], af[cur][tm][1], af[cur][tm][2], af[cur][tm][3],
                              bf[cur][tn][0], bf[cur][tn][1]);
        }

        // issue stage kt+3 (overwrites stage used at compute kt-1; safe with
        // the single sync at loop top given STAGES=4)
        {
            const int kn = kt + STAGES - 1;
            if (kn < nkt) {
                const int sn = kn & (STAGES - 1);
                const uint32_t so = (uint32_t)(sn * STAGE_FLOATS) * 4u;
                cpasync16(Asd + so, Agp + kn * BK);
                cpasync16(Asd + so + 32u * ASTR * 4u, Agp + (size_t)32 * lda + kn * BK);
                #pragma unroll
                for (int p = 0; p < 4; p++)
                    cpasync16(Bsd + so + (uint32_t)(p * 8 * BSTR) * 4u,
                              Bgp + (size_t)(kn * BK + p * 8) * ldb);
            }
            asm volatile("cp.async.commit_group;");
        }
    }

    // epilogue
    const int relu  = mode & 1;
    const int rnd   = mode & 2;
    const int part  = mode & 4;
    #pragma unroll
    for (int tm = 0; tm < 2; tm++) {
        const int rbase = m0 + wm * 32 + tm * 16 + gid;
        #pragma unroll
        for (int tn = 0; tn < 4; tn++) {
            const int cb = n0 + wn * 32 + tn * 8 + tig * 2;
            float b0 = 0.0f, b1 = 0.0f;
            if (!part) { b0 = bias[cb]; b1 = bias[cb + 1]; }
            float v0 = acc[tm][tn][0] + b0, v1 = acc[tm][tn][1] + b1;
            float v2 = acc[tm][tn][2] + b0, v3 = acc[tm][tn][3] + b1;
            if (relu) {
                v0 = fmaxf(v0, 0.0f); v1 = fmaxf(v1, 0.0f);
                v2 = fmaxf(v2, 0.0f); v3 = fmaxf(v3, 0.0f);
            }
            if (rnd) {
                v0 = tf32r(v0); v1 = tf32r(v1);
                v2 = tf32r(v2); v3 = tf32r(v3);
            }
            *(float2*)(C + (size_t)rbase * N + cb)       = make_float2(v0, v1);
            *(float2*)(C + (size_t)(rbase + 8) * N + cb) = make_float2(v2, v3);
        }
    }
}

// ---------------------------------------------------------------------------
// Pack head weights: Whead[k][0:84]=Wloc, [84:105]=Wcls, [105:128]=0.
// (rounding handled by the GEMM's B-fragment cvt)
// ---------------------------------------------------------------------------
__global__ __launch_bounds__(256) void pack_head_kernel(
    const float* __restrict__ Wloc, const float* __restrict__ Wcls,
    float* __restrict__ Wh)
{
    const int idx = blockIdx.x * 256 + threadIdx.x;
    const int k = idx >> 7;
    const int j = idx & 127;
    float v = 0.0f;
    if (j < NLOC)       v = Wloc[(size_t)k * NLOC + j];
    else if (j < NHEAD) v = Wcls[(size_t)k * NCLS + (j - NLOC)];
    Wh[idx] = v;
}

// ---------------------------------------------------------------------------
// Reduce head split-K partials, add bias, scatter into output layout
// [256*84 loc][256*21 cls].
// ---------------------------------------------------------------------------
__global__ __launch_bounds__(128) void reduce_head_kernel(
    const float* __restrict__ part,
    const float* __restrict__ bloc, const float* __restrict__ bcls,
    float* __restrict__ out)
{
    const int n = blockIdx.x;
    const int j = threadIdx.x;
    if (j >= NHEAD) return;
    float s = (j < NLOC) ? bloc[j] : bcls[j - NLOC];
    #pragma unroll
    for (int p = 0; p < HSPLIT; p++)
        s += part[(size_t)p * N_ROI * NHPAD + (size_t)n * NHPAD + j];
    if (j < NLOC)
        out[(size_t)n * NLOC + j] = s;
    else
        out[(size_t)N_ROI * NLOC + (size_t)n * NCLS + (j - NLOC)] = s;
}

// ---------------------------------------------------------------------------
extern "C" void kernel_launch(void* const* d_in, const int* in_sizes, int n_in,
                              void* d_out, int out_size)
{
    const float* f3   = (const float*)d_in[0];
    const float* f4   = (const float*)d_in[1];
    const float* f5   = (const float*)d_in[2];
    const float* rois = (const float*)d_in[3];
    const float* Wfc6 = (const float*)d_in[4];
    const float* bfc6 = (const float*)d_in[5];
    const float* Wfc7 = (const float*)d_in[6];
    const float* bfc7 = (const float*)d_in[7];
    const float* Wloc = (const float*)d_in[8];
    const float* bloc = (const float*)d_in[9];
    const float* Wcls = (const float*)d_in[10];
    const float* bcls = (const float*)d_in[11];
    float* out = (float*)d_out;

    float *pooled, *fc6, *fc7, *whead, *headpart;
    cudaGetSymbolAddress((void**)&pooled, g_pooled);
    cudaGetSymbolAddress((void**)&fc6, g_fc6);
    cudaGetSymbolAddress((void**)&fc7, g_fc7);
    cudaGetSymbolAddress((void**)&whead, g_whead);
    cudaGetSymbolAddress((void**)&headpart, g_headpart);

    cudaFuncSetAttribute(gemm_tf32_kernel,
                         cudaFuncAttributeMaxDynamicSharedMemorySize, SMEM_BYTES);

    // 0) pack head weights
    pack_head_kernel<<<(DH * NHPAD) / 256, 256>>>(Wloc, Wcls, whead);

    // 1) roi_pool (tf32-rounded output)
    roi_pool_kernel<<<N_ROI, CCH>>>(f3, f4, f5, rois, pooled);

    // 2) fc6 = relu(pooled @ Wfc6 + b)  (M=256, K=12544, N=4096), mode relu|round
    gemm_tf32_kernel<<<dim3(DH / BN, N_ROI / BM, 1), TPB, SMEM_BYTES>>>(
        pooled, Wfc6, bfc6, fc6, N_ROI, DH, DIN, DH, DIN, 3);

    // 3) fc7 = relu(fc6 @ Wfc7 + b)    (M=256, K=4096, N=4096), mode relu|round
    gemm_tf32_kernel<<<dim3(DH / BN, N_ROI / BM, 1), TPB, SMEM_BYTES>>>(
        fc6, Wfc7, bfc7, fc7, N_ROI, DH, DH, DH, DH, 3);

    // 4) head partials = fc7 @ Whead   (M=256, N=128, K split 16x256), mode partial
    gemm_tf32_kernel<<<dim3(NHPAD / BN, N_ROI / BM, HSPLIT), TPB, SMEM_BYTES>>>(
        fc7, whead, nullptr, headpart, N_ROI, NHPAD, DH, NHPAD, DH / HSPLIT, 4);

    // 5) reduce + bias + scatter
    reduce_head_kernel<<<N_ROI, 128>>>(headpart, bloc, bcls, out);
}